// round 5
// baseline (speedup 1.0000x reference)
#include <cuda_runtime.h>
#include <math.h>
#include <stdint.h>

#define BB   1024      // batch rows
#define NN   8192      // samples per row
#define MM2  900       // half fold period (parity decimation)
#define NB   140       // bpm bins
#define NBP  144       // padded bins
#define NCH  9         // m-chunks
#define CHM  100       // m per chunk (9*100 = 900)
#define SLAB 10        // m per smem slab

// ---------------- device scratch ----------------
__device__ float  d_hann[NN];
__device__ float2 d_fold[(size_t)BB * MM2];             // (ge, go) per (row, m)
__device__ float2 d_part[(size_t)BB * NCH * NBP];       // [row][chunk][bin] (s,c)
__device__ float  d_tl[BB];                             // per-row (1 - pearson)
__device__ float  d_fl[BB];                             // per-row (ce + kl)
__device__ unsigned int d_done;

typedef unsigned long long ull;

// ---------------- f32x2 helpers ----------------
__device__ __forceinline__ ull pk2(float lo, float hi) {
    ull r;
    asm("mov.b64 %0, {%1, %2};" : "=l"(r) : "f"(lo), "f"(hi));
    return r;
}
__device__ __forceinline__ void fma2(ull& d, ull a, ull b) {
    asm("fma.rn.f32x2 %0, %1, %2, %0;" : "+l"(d) : "l"(a), "l"(b));
}

// ---------------- warp helpers ----------------
__device__ __forceinline__ float wsum(float v) {
    #pragma unroll
    for (int o = 16; o; o >>= 1) v += __shfl_down_sync(0xffffffffu, v, o);
    return v;
}
__device__ __forceinline__ float wallsum(float v) {
    #pragma unroll
    for (int o = 16; o; o >>= 1) v += __shfl_xor_sync(0xffffffffu, v, o);
    return v;
}
__device__ __forceinline__ float wallmax(float v) {
    #pragma unroll
    for (int o = 16; o; o >>= 1) v = fmaxf(v, __shfl_xor_sync(0xffffffffu, v, o));
    return v;
}

// ---------------- K0: hann table + ticket reset ----------------
__global__ void __launch_bounds__(256) k_init() {
    int n = blockIdx.x * 256 + threadIdx.x;
    if (n < NN) {
        float s = sinf((float)n * 3.8349520e-4f);   // pi/8191
        d_hann[n] = s * s;
    }
    if (n == 0) d_done = 0;
}

// ---------------- K1: pearson sums + parity fold (no smem row buffer) --------
__global__ void __launch_bounds__(256) k_fold(const float* __restrict__ x,
                                              const float* __restrict__ y) {
    __shared__ float red[8][5];
    int b = blockIdx.x;
    int tid = threadIdx.x;
    int lane = tid & 31, warp = tid >> 5;

    const float* xr = x + (size_t)b * NN;
    const float* yr = y + (size_t)b * NN;

    float sx = 0.f, sy = 0.f, sxy = 0.f, sxx = 0.f, syy = 0.f;

    #pragma unroll 1
    for (int m = tid; m < MM2; m += 256) {
        float ge = 0.f, go = 0.f;
        #pragma unroll
        for (int j = 0; j < 10; j++) {
            int n = m + 900 * j;
            if (j < 9 || n < NN) {
                float xv = xr[n], yv = yr[n];
                sx  += xv;       sy  += yv;
                sxy += xv * yv;  sxx += xv * xv;  syy += yv * yv;
                float hx = xv * d_hann[n];
                ge += hx;
                go += (j & 1) ? -hx : hx;
            }
        }
        d_fold[(size_t)b * MM2 + m] = make_float2(ge, go);
    }

    sx = wsum(sx); sy = wsum(sy); sxy = wsum(sxy); sxx = wsum(sxx); syy = wsum(syy);
    if (lane == 0) { red[warp][0]=sx; red[warp][1]=sy; red[warp][2]=sxy; red[warp][3]=sxx; red[warp][4]=syy; }
    __syncthreads();
    if (tid == 0) {
        double SX=0, SY=0, SXY=0, SXX=0, SYY=0;
        #pragma unroll
        for (int w = 0; w < 8; w++) {
            SX += red[w][0]; SY += red[w][1]; SXY += red[w][2];
            SXX += red[w][3]; SYY += red[w][4];
        }
        double num = (double)NN * SXY - SX * SY;
        double den = sqrt(((double)NN * SXX - SX * SX) * ((double)NN * SYY - SY * SY));
        d_tl[b] = (float)(1.0 - num / den);
    }
}

// ---------------- K2: 900-point parity NUDFT, f32x2, in-kernel tables --------
// grid (32 row-tiles, 9 chunks), block 288 = 36 tx * 8 ty; tile 4 rows x 4 bins
__global__ void __launch_bounds__(288, 2) k_dft() {
    __shared__ float sTab[SLAB * 2 * NBP];    // 10 m x 144 bins x (s,c)
    __shared__ float sGe[SLAB][32];
    __shared__ float sGo[SLAB][32];

    int tile  = blockIdx.x;
    int chunk = blockIdx.y;
    int tid = threadIdx.x;
    int tx = tid % 36;
    int ty = tid / 36;

    int rowBase = tile * 32;
    int mBase = chunk * CHM;

    int bk  = tid % 144;
    int grp = tid / 144;
    int freq = 40 + bk;

    ull acc[4][4] = {};
    const float* gp = (tx & 1) ? &sGo[0][0] : &sGe[0][0];
    const float ASCALE = 3.4906585e-3f;   // 2*pi/1800

    for (int step = 0; step < CHM / SLAB; step++) {
        int m0 = mBase + step * SLAB;
        __syncthreads();
        #pragma unroll
        for (int i = 0; i < 5; i++) {
            int mi = grp * 5 + i;
            float s = 0.f, c = 0.f;
            if (bk < NB) {
                int r = (freq * (m0 + mi)) % 1800;
                if (r >= 900) r -= 1800;
                __sincosf((float)r * ASCALE, &s, &c);
            }
            sTab[mi * (2 * NBP) + 2 * bk]     = s;
            sTab[mi * (2 * NBP) + 2 * bk + 1] = c;
        }
        if (tid < 160) {
            int r = tid & 31, q = tid >> 5;
            float4 v = *(const float4*)(d_fold + (size_t)(rowBase + r) * MM2 + m0 + 2 * q);
            sGe[2 * q][r]     = v.x;  sGo[2 * q][r]     = v.y;
            sGe[2 * q + 1][r] = v.z;  sGo[2 * q + 1][r] = v.w;
        }
        __syncthreads();

        #pragma unroll
        for (int mi = 0; mi < SLAB; mi++) {
            float4 g = *(const float4*)&gp[mi * 32 + 4 * ty];
            const ull* trow = (const ull*)&sTab[mi * (2 * NBP)];
            ull p0 = trow[tx];
            ull p1 = trow[tx + 36];
            ull p2 = trow[tx + 72];
            ull p3 = trow[tx + 108];
            float gr[4] = {g.x, g.y, g.z, g.w};
            #pragma unroll
            for (int r = 0; r < 4; r++) {
                ull g2 = pk2(gr[r], gr[r]);
                fma2(acc[r][0], g2, p0);
                fma2(acc[r][1], g2, p1);
                fma2(acc[r][2], g2, p2);
                fma2(acc[r][3], g2, p3);
            }
        }
    }

    #pragma unroll
    for (int r = 0; r < 4; r++) {
        int row = rowBase + 4 * ty + r;
        ull* dst = (ull*)(d_part + ((size_t)row * NCH + chunk) * NBP);
        dst[tx]       = acc[r][0];
        dst[tx + 36]  = acc[r][1];
        dst[tx + 72]  = acc[r][2];
        dst[tx + 108] = acc[r][3];
    }
}

// ---------------- K3: one block per row; thread = bin ------------------------
#define LT 160   // threads (5 warps); bins 0..143 active
__global__ void __launch_bounds__(LT) k_loss(const int* __restrict__ hr,
                                             const int* __restrict__ epoch_p,
                                             float* __restrict__ out) {
    __shared__ float sh[8];
    __shared__ float shB[2];           // [0]=broadcast scalar, [1]=logit[h]
    int tid = threadIdx.x;
    int lane = tid & 31, warp = tid >> 5;
    int row = blockIdx.x;
    bool valid = tid < NB;

    // sum chunk partials for this bin (coalesced, MLP=9)
    float s = 0.f, c = 0.f;
    if (valid) {
        const float2* pr = d_part + (size_t)row * NCH * NBP + tid;
        #pragma unroll
        for (int ch = 0; ch < NCH; ch++) {
            float2 v = pr[ch * NBP];
            s += v.x; c += v.y;
        }
    }
    float ca = valid ? (s * s + c * c) : 0.f;

    // tot = sum(ca)
    float v = wallsum(ca);
    if (lane == 0) sh[warp] = v;
    __syncthreads();
    float tot = sh[0] + sh[1] + sh[2] + sh[3] + sh[4];
    __syncthreads();

    float logit = ca / tot;            // garbage for invalid lanes; masked below

    // mx = max(logit)
    v = wallmax(valid ? logit : -1e30f);
    if (lane == 0) sh[warp] = v;
    __syncthreads();
    float mx = fmaxf(fmaxf(fmaxf(sh[0], sh[1]), fmaxf(sh[2], sh[3])), sh[4]);
    __syncthreads();

    // se = sum(exp(logit - mx))
    v = wallsum(valid ? expf(logit - mx) : 0.f);
    if (lane == 0) sh[warp] = v;
    __syncthreads();
    float lse = mx + logf(sh[0] + sh[1] + sh[2] + sh[3] + sh[4]);

    int h = hr[row];
    if (tid == h) shB[1] = logit;
    __syncthreads();
    float ce = lse - shB[1];
    __syncthreads();

    // kl
    float klc = 0.f;
    if (valid) {
        float dd = (float)tid - (float)h;
        float t = expf(-0.5f * dd * dd) * 0.3989422804014327f;
        t = fmaxf(t, 1e-15f);
        klc = expf(t) * (t - (logit - lse));
    }
    v = wallsum(klc);
    if (lane == 0) sh[warp] = v;
    __syncthreads();
    float kl = (sh[0] + sh[1] + sh[2] + sh[3] + sh[4]) / (float)NB;

    if (tid == 0) d_fl[row] = ce + kl;

    // ---- last-block final reduction ----
    __threadfence();
    __syncthreads();
    __shared__ unsigned int sTicket;
    if (tid == 0) sTicket = atomicAdd(&d_done, 1u);
    __syncthreads();
    if (sTicket != gridDim.x - 1) return;
    __threadfence();

    float a = 0.f, cc = 0.f;
    for (int i = tid; i < BB; i += LT) { a += d_tl[i]; cc += d_fl[i]; }
    a = wallsum(a); cc = wallsum(cc);
    __syncthreads();
    if (lane == 0) { sh[warp] = a; sh[warp + 5 > 7 ? 7 : warp] = sh[warp]; }
    __syncthreads();
    __shared__ float sA[5], sC[5];
    if (lane == 0) { sA[warp] = a; sC[warp] = cc; }
    __syncthreads();
    if (tid == 0) {
        double TA = 0.0, TC = 0.0;
        #pragma unroll
        for (int w = 0; w < 5; w++) { TA += sA[w]; TC += sC[w]; }
        double tl = TA / (double)BB;
        double fl = TC / (double)BB;
        int epoch = epoch_p[0];
        double alpha, beta;
        if (epoch > 25) { alpha = 0.05; beta = 2.0; }
        else {
            alpha = 0.1 * pow(0.5, (double)epoch / 25.0);
            beta  = pow(2.0, (double)epoch / 25.0);
        }
        out[0] = (float)(alpha * tl + beta * fl);
    }
}

// ---------------- launch ----------------
extern "C" void kernel_launch(void* const* d_in, const int* in_sizes, int n_in,
                              void* d_out, int out_size) {
    const int*   epoch_p = nullptr;
    const float* xp = nullptr;
    const float* yp = nullptr;
    const int*   hrp = nullptr;
    for (int i = 0; i < n_in; i++) {
        if (in_sizes[i] == 1 && !epoch_p) epoch_p = (const int*)d_in[i];
        else if (in_sizes[i] == BB * NN) { if (!xp) xp = (const float*)d_in[i]; else yp = (const float*)d_in[i]; }
        else if (in_sizes[i] == BB) hrp = (const int*)d_in[i];
    }
    float* out = (float*)d_out;

    k_init<<<(NN + 255) / 256, 256>>>();
    k_fold<<<BB, 256>>>(xp, yp);
    k_dft<<<dim3(32, NCH), 288>>>();
    k_loss<<<BB, LT>>>(hrp, epoch_p, out);
    (void)out_size;
}